// round 1
// baseline (speedup 1.0000x reference)
#include <cuda_runtime.h>

#define DIM   2048
#define BATCH 32768

// Scratch: one branch's hidden activations at a time (kernels are stream-serial),
// plus logits for all 3 branches. Device globals per allocation rules.
__device__ __align__(16) float g_H[(size_t)BATCH * DIM];        // 256 MB
__device__ __align__(16) float g_logits[3 * BATCH * 2];

// ---------------------------------------------------------------------------
// SGEMM: C[m,n] = sum_k A[m,k] * W[n,k] + bias[n]
// A: [M,K] row-major (x), W: [N,K] row-major (W1), C: [M,N]
// 128x128 tile, BK=16, 256 threads, 8x8 per-thread micro-tile (split 4+4),
// register-prefetch double buffering.
// ---------------------------------------------------------------------------
__global__ __launch_bounds__(256, 2)
void gemm128_bias(const float* __restrict__ A, const float* __restrict__ W,
                  const float* __restrict__ bias, float* __restrict__ C,
                  int M, int N, int K)
{
    __shared__ __align__(16) float As[16][128];
    __shared__ __align__(16) float Bs[16][128];

    const int tid = threadIdx.x;
    const int tx  = tid & 15;    // 0..15 -> n frag
    const int ty  = tid >> 4;    // 0..15 -> m frag
    const int m0  = blockIdx.y << 7;
    const int n0  = blockIdx.x << 7;

    // tile-load mapping: 256 threads, each loads 8 floats (2 x float4) of A and W
    const int lrow = tid >> 1;           // 0..127
    const int lk   = (tid & 1) << 3;     // 0 or 8

    const float* Ab = A + (size_t)(m0 + lrow) * K + lk;
    const float* Wb = W + (size_t)(n0 + lrow) * K + lk;

    float acc[8][8];
#pragma unroll
    for (int i = 0; i < 8; i++)
#pragma unroll
        for (int j = 0; j < 8; j++) acc[i][j] = 0.f;

    // prefetch tile 0
    float4 pa0 = *(const float4*)(Ab);
    float4 pa1 = *(const float4*)(Ab + 4);
    float4 pb0 = *(const float4*)(Wb);
    float4 pb1 = *(const float4*)(Wb + 4);

    for (int kt = 0; kt < K; kt += 16) {
        // commit prefetched tile (transposed: [k][m])
        As[lk + 0][lrow] = pa0.x; As[lk + 1][lrow] = pa0.y;
        As[lk + 2][lrow] = pa0.z; As[lk + 3][lrow] = pa0.w;
        As[lk + 4][lrow] = pa1.x; As[lk + 5][lrow] = pa1.y;
        As[lk + 6][lrow] = pa1.z; As[lk + 7][lrow] = pa1.w;
        Bs[lk + 0][lrow] = pb0.x; Bs[lk + 1][lrow] = pb0.y;
        Bs[lk + 2][lrow] = pb0.z; Bs[lk + 3][lrow] = pb0.w;
        Bs[lk + 4][lrow] = pb1.x; Bs[lk + 5][lrow] = pb1.y;
        Bs[lk + 6][lrow] = pb1.z; Bs[lk + 7][lrow] = pb1.w;
        __syncthreads();

        if (kt + 16 < K) {   // prefetch next tile while computing this one
            pa0 = *(const float4*)(Ab + kt + 16);
            pa1 = *(const float4*)(Ab + kt + 20);
            pb0 = *(const float4*)(Wb + kt + 16);
            pb1 = *(const float4*)(Wb + kt + 20);
        }

#pragma unroll
        for (int kk = 0; kk < 16; kk++) {
            float4 a0 = *(const float4*)&As[kk][ty * 4];
            float4 a1 = *(const float4*)&As[kk][ty * 4 + 64];
            float4 b0 = *(const float4*)&Bs[kk][tx * 4];
            float4 b1 = *(const float4*)&Bs[kk][tx * 4 + 64];
            float am[8] = {a0.x, a0.y, a0.z, a0.w, a1.x, a1.y, a1.z, a1.w};
            float bn[8] = {b0.x, b0.y, b0.z, b0.w, b1.x, b1.y, b1.z, b1.w};
#pragma unroll
            for (int i = 0; i < 8; i++)
#pragma unroll
                for (int j = 0; j < 8; j++)
                    acc[i][j] += am[i] * bn[j];
        }
        __syncthreads();
    }

    float4 bb0 = *(const float4*)(bias + n0 + tx * 4);
    float4 bb1 = *(const float4*)(bias + n0 + tx * 4 + 64);
#pragma unroll
    for (int i = 0; i < 8; i++) {
        int m = m0 + ((i < 4) ? (ty * 4 + i) : (64 + ty * 4 + (i - 4)));
        float4 o0 = make_float4(acc[i][0] + bb0.x, acc[i][1] + bb0.y,
                                acc[i][2] + bb0.z, acc[i][3] + bb0.w);
        float4 o1 = make_float4(acc[i][4] + bb1.x, acc[i][5] + bb1.y,
                                acc[i][6] + bb1.z, acc[i][7] + bb1.w);
        *(float4*)(C + (size_t)m * N + n0 + tx * 4)      = o0;
        *(float4*)(C + (size_t)m * N + n0 + tx * 4 + 64) = o1;
    }
}

// ---------------------------------------------------------------------------
// Block reduction of two floats (sum), 256 threads.
// ---------------------------------------------------------------------------
__device__ __forceinline__ float2 block_reduce2(float a, float b)
{
    __shared__ float sa[8], sb[8];
    __syncthreads();   // protect smem reuse across calls
    int lane = threadIdx.x & 31, wid = threadIdx.x >> 5;
#pragma unroll
    for (int o = 16; o; o >>= 1) {
        a += __shfl_down_sync(0xFFFFFFFFu, a, o);
        b += __shfl_down_sync(0xFFFFFFFFu, b, o);
    }
    if (lane == 0) { sa[wid] = a; sb[wid] = b; }
    __syncthreads();
    if (wid == 0) {
        a = (lane < 8) ? sa[lane] : 0.f;
        b = (lane < 8) ? sb[lane] : 0.f;
#pragma unroll
        for (int o = 4; o; o >>= 1) {
            a += __shfl_down_sync(0xFFFFFFFFu, a, o);
            b += __shfl_down_sync(0xFFFFFFFFu, b, o);
        }
        if (lane == 0) { sa[0] = a; sb[0] = b; }
    }
    __syncthreads();
    return make_float2(sa[0], sb[0]);
}

// ---------------------------------------------------------------------------
// Per-row LayerNorm + ReLU + Linear(D->2). One block per row, 256 threads,
// each thread owns 8 contiguous columns (2 x float4). D = 2048 exactly.
// ---------------------------------------------------------------------------
__global__ __launch_bounds__(256)
void ln_relu_head(const float* __restrict__ H,
                  const float* __restrict__ gamma, const float* __restrict__ beta,
                  const float* __restrict__ W2, const float* __restrict__ b2,
                  float* __restrict__ logits)
{
    const int row = blockIdx.x;
    const int t   = threadIdx.x;
    const float4* h4 = (const float4*)(H + (size_t)row * DIM);

    float4 v0 = h4[t * 2];
    float4 v1 = h4[t * 2 + 1];

    float s  = v0.x + v0.y + v0.z + v0.w + v1.x + v1.y + v1.z + v1.w;
    float ss = v0.x * v0.x + v0.y * v0.y + v0.z * v0.z + v0.w * v0.w
             + v1.x * v1.x + v1.y * v1.y + v1.z * v1.z + v1.w * v1.w;

    float2 r = block_reduce2(s, ss);
    const float inv_d = 1.f / (float)DIM;
    float mu   = r.x * inv_d;
    float var  = r.y * inv_d - mu * mu;
    float rinv = rsqrtf(var + 1e-5f);

    const float4* g4  = (const float4*)gamma;
    const float4* be4 = (const float4*)beta;
    const float4* w0  = (const float4*)W2;
    const float4* w1  = (const float4*)(W2 + DIM);

    float l0 = 0.f, l1 = 0.f;
    {
        float4 g = g4[t * 2], be = be4[t * 2], wa = w0[t * 2], wb = w1[t * 2];
        float h;
        h = fmaxf(fmaf((v0.x - mu) * rinv, g.x, be.x), 0.f); l0 += h * wa.x; l1 += h * wb.x;
        h = fmaxf(fmaf((v0.y - mu) * rinv, g.y, be.y), 0.f); l0 += h * wa.y; l1 += h * wb.y;
        h = fmaxf(fmaf((v0.z - mu) * rinv, g.z, be.z), 0.f); l0 += h * wa.z; l1 += h * wb.z;
        h = fmaxf(fmaf((v0.w - mu) * rinv, g.w, be.w), 0.f); l0 += h * wa.w; l1 += h * wb.w;
    }
    {
        float4 g = g4[t * 2 + 1], be = be4[t * 2 + 1], wa = w0[t * 2 + 1], wb = w1[t * 2 + 1];
        float h;
        h = fmaxf(fmaf((v1.x - mu) * rinv, g.x, be.x), 0.f); l0 += h * wa.x; l1 += h * wb.x;
        h = fmaxf(fmaf((v1.y - mu) * rinv, g.y, be.y), 0.f); l0 += h * wa.y; l1 += h * wb.y;
        h = fmaxf(fmaf((v1.z - mu) * rinv, g.z, be.z), 0.f); l0 += h * wa.z; l1 += h * wb.z;
        h = fmaxf(fmaf((v1.w - mu) * rinv, g.w, be.w), 0.f); l0 += h * wa.w; l1 += h * wb.w;
    }

    float2 lr = block_reduce2(l0, l1);
    if (t == 0) {
        logits[row * 2 + 0] = lr.x + b2[0];
        logits[row * 2 + 1] = lr.y + b2[1];
    }
}

// ---------------------------------------------------------------------------
// route = argmax(first_logits) (ties -> index 0); route==0 -> fake else real
// ---------------------------------------------------------------------------
__global__ void combine_kernel(const float* __restrict__ lf,
                               const float* __restrict__ lfake,
                               const float* __restrict__ lreal,
                               float* __restrict__ out, int B)
{
    int b = blockIdx.x * blockDim.x + threadIdx.x;
    if (b >= B) return;
    float2 f = ((const float2*)lf)[b];
    const float2* src = (f.x >= f.y) ? (const float2*)lfake : (const float2*)lreal;
    ((float2*)out)[b] = src[b];
}

// ---------------------------------------------------------------------------
extern "C" void kernel_launch(void* const* d_in, const int* in_sizes, int n_in,
                              void* d_out, int out_size)
{
    (void)in_sizes; (void)n_in; (void)out_size;
    const float* x = (const float*)d_in[0];

    float* H = nullptr;
    float* L = nullptr;
    cudaGetSymbolAddress((void**)&H, g_H);
    cudaGetSymbolAddress((void**)&L, g_logits);

    dim3 grid(DIM / 128, BATCH / 128);   // (16, 256)

    for (int br = 0; br < 3; br++) {
        const float* W1 = (const float*)d_in[1 + br * 6 + 0];
        const float* b1 = (const float*)d_in[1 + br * 6 + 1];
        const float* lg = (const float*)d_in[1 + br * 6 + 2];
        const float* lb = (const float*)d_in[1 + br * 6 + 3];
        const float* W2 = (const float*)d_in[1 + br * 6 + 4];
        const float* b2 = (const float*)d_in[1 + br * 6 + 5];

        gemm128_bias<<<grid, 256>>>(x, W1, b1, H, BATCH, DIM, DIM);
        ln_relu_head<<<BATCH, 256>>>(H, lg, lb, W2, b2, L + (size_t)br * BATCH * 2);
    }

    combine_kernel<<<(BATCH + 255) / 256, 256>>>(
        L, L + (size_t)BATCH * 2, L + (size_t)2 * BATCH * 2, (float*)d_out, BATCH);
}

// round 3
// speedup vs baseline: 1.8463x; 1.8463x over previous
#include <cuda_runtime.h>
#include <cuda_bf16.h>
#include <cstdint>

#define DIM   2048
#define BATCH 32768

// ---------------------------------------------------------------------------
// Device-global scratch (allocation-free rule)
// ---------------------------------------------------------------------------
__device__ __align__(16) float g_H[(size_t)BATCH * DIM];                 // 256 MB
__device__ __align__(16) float g_logits[3 * BATCH * 2];
__device__ __align__(16) __nv_bfloat16 g_xs[3][(size_t)BATCH * DIM];    // x splits hi/mid/lo
__device__ __align__(16) __nv_bfloat16 g_ws[3][(size_t)DIM * DIM];      // W1 splits

// ---------------------------------------------------------------------------
// helpers
// ---------------------------------------------------------------------------
__device__ __forceinline__ uint32_t smem_u32_of(const void* p) {
    uint32_t a;
    asm("{ .reg .u64 t; cvta.to.shared.u64 t, %1; cvt.u32.u64 %0, t; }" : "=r"(a) : "l"(p));
    return a;
}
__device__ __forceinline__ void cp16(uint32_t dst, const void* src) {
    asm volatile("cp.async.cg.shared.global [%0], [%1], 16;" :: "r"(dst), "l"(src));
}
__device__ __forceinline__ void ldsm_x4(uint32_t* r, uint32_t addr) {
    asm volatile("ldmatrix.sync.aligned.m8n8.x4.shared.b16 {%0,%1,%2,%3}, [%4];"
                 : "=r"(r[0]), "=r"(r[1]), "=r"(r[2]), "=r"(r[3]) : "r"(addr));
}
__device__ __forceinline__ void mma16816(float* c, const uint32_t* a,
                                         uint32_t b0, uint32_t b1) {
    asm volatile("mma.sync.aligned.m16n8k16.row.col.f32.bf16.bf16.f32 "
                 "{%0,%1,%2,%3}, {%4,%5,%6,%7}, {%8,%9}, {%0,%1,%2,%3};"
                 : "+f"(c[0]), "+f"(c[1]), "+f"(c[2]), "+f"(c[3])
                 : "r"(a[0]), "r"(a[1]), "r"(a[2]), "r"(a[3]), "r"(b0), "r"(b1));
}
// Swizzle<3,4,3>: conflict-free ldmatrix on 64B-row tiles
__device__ __forceinline__ uint32_t swz(uint32_t off) {
    return off ^ (((off >> 7) & 7u) << 4);
}

// ---------------------------------------------------------------------------
// Split-bf16 GEMM via mma.sync (HMMA):  C[m,n] = sum_k A[m,k]*W[n,k] + bias[n]
// Virtual-K mainloop over NPROD products x 64 k-tiles of BK=32.
// Tile 128x128, 8 warps (warp tile 64x32), 4-stage cp.async pipeline.
// ---------------------------------------------------------------------------
template<int NSPLIT>
__global__ __launch_bounds__(256)
void gemm_mma(const __nv_bfloat16* __restrict__ Ah, const __nv_bfloat16* __restrict__ Am,
              const __nv_bfloat16* __restrict__ Al,
              const __nv_bfloat16* __restrict__ Bh, const __nv_bfloat16* __restrict__ Bm,
              const __nv_bfloat16* __restrict__ Bl,
              const float* __restrict__ bias, float* __restrict__ C)
{
    constexpr int NPROD = (NSPLIT == 2) ? 3 : 6;
    constexpr int KT    = DIM / 32;            // 64 k-tiles per product
    constexpr int T     = NPROD * KT;          // total pipeline stages
    constexpr int STAGE = 16384;               // 8KB A + 8KB B

    extern __shared__ __align__(128) char smem[];
    const uint32_t sbase = smem_u32_of(smem);

    const int tid = threadIdx.x;
    const int wid = tid >> 5, lid = tid & 31;
    const int wm  = wid >> 2;                  // 0..1  (m warp)
    const int wn  = wid & 3;                   // 0..3  (n warp)
    const int m0  = blockIdx.y * 128;
    const int n0  = blockIdx.x * 128;

    // product schedule: which split of A and B per product
    const int PA[6] = {0, 0, 1, 1, 0, 2};
    const int PB[6] = {0, 1, 0, 1, 2, 0};

    const __nv_bfloat16* Abase[3] = {Ah, Am, Al};
    const __nv_bfloat16* Bbase[3] = {Bh, Bm, Bl};

    // loader mapping: 1024 granules of 16B per stage (512 A + 512 B); 4/thread
    const int lrow = tid >> 2;          // 0..63 base row (x2 halves)
    const int lch  = tid & 3;           // 16B chunk within 64B row

    auto load_stage = [&](int t, int buf) {
        const int p  = t / KT;
        const int kt = t % KT;
        const size_t kofs = (size_t)kt * 32 + lch * 8;
        const __nv_bfloat16* As = Abase[PA[p]];
        const __nv_bfloat16* Bs = Bbase[PB[p]];
        const uint32_t sa = sbase + buf * STAGE;
        const uint32_t sb = sa + 8192;
        // A rows lrow and lrow+64
        cp16(sa + swz((uint32_t)lrow * 64 + lch * 16),
             As + (size_t)(m0 + lrow) * DIM + kofs);
        cp16(sa + swz((uint32_t)(lrow + 64) * 64 + lch * 16),
             As + (size_t)(m0 + lrow + 64) * DIM + kofs);
        // B rows lrow and lrow+64
        cp16(sb + swz((uint32_t)lrow * 64 + lch * 16),
             Bs + (size_t)(n0 + lrow) * DIM + kofs);
        cp16(sb + swz((uint32_t)(lrow + 64) * 64 + lch * 16),
             Bs + (size_t)(n0 + lrow + 64) * DIM + kofs);
        asm volatile("cp.async.commit_group;" ::: "memory");
    };

    float acc[4][4][4];
#pragma unroll
    for (int i = 0; i < 4; i++)
#pragma unroll
        for (int j = 0; j < 4; j++)
#pragma unroll
            for (int r = 0; r < 4; r++) acc[i][j][r] = 0.f;

    // ldmatrix per-lane address components
    // A frag (m16k16): row = wm*64 + mf*16 + (l%8) + ((l>>3)&1)*8 ; kbyte = ks*32 + (l>>4)*16
    // B frag (n16k16): row = wn*32 + ng*16 + (l%8) + ((l>>4)&1)*8 ; kbyte = ks*32 + ((l>>3)&1)*16
    const uint32_t a_row = wm * 64 + (lid & 7) + ((lid >> 3) & 1) * 8;
    const uint32_t a_kb  = ((lid >> 4) & 1) * 16;
    const uint32_t b_row = wn * 32 + (lid & 7) + ((lid >> 4) & 1) * 8;
    const uint32_t b_kb  = ((lid >> 3) & 1) * 16;

    // prime pipeline: 3 stages
    load_stage(0, 0);
    load_stage(1, 1);
    load_stage(2, 2);

    for (int t = 0; t < T; t++) {
        asm volatile("cp.async.wait_group 2;" ::: "memory");
        __syncthreads();

        const uint32_t sa = sbase + (t & 3) * STAGE;
        const uint32_t sb = sa + 8192;

#pragma unroll
        for (int ks = 0; ks < 2; ks++) {
            uint32_t af[4][4], bf[2][4];
#pragma unroll
            for (int mf = 0; mf < 4; mf++)
                ldsm_x4(af[mf], sa + swz((a_row + mf * 16) * 64 + ks * 32 + a_kb));
#pragma unroll
            for (int ng = 0; ng < 2; ng++)
                ldsm_x4(bf[ng], sb + swz((b_row + ng * 16) * 64 + ks * 32 + b_kb));
#pragma unroll
            for (int mf = 0; mf < 4; mf++)
#pragma unroll
                for (int nf = 0; nf < 4; nf++)
                    mma16816(acc[mf][nf], af[mf],
                             bf[nf >> 1][(nf & 1) * 2], bf[nf >> 1][(nf & 1) * 2 + 1]);
        }

        if (t + 3 < T) load_stage(t + 3, (t + 3) & 3);
    }

    // epilogue: add bias, store fp32 C
    const int er = lid >> 2;            // 0..7
    const int ec = (lid & 3) * 2;       // 0,2,4,6
#pragma unroll
    for (int mf = 0; mf < 4; mf++) {
#pragma unroll
        for (int nf = 0; nf < 4; nf++) {
            const int col = n0 + wn * 32 + nf * 8 + ec;
            const float bx = __ldg(&bias[col]);
            const float by = __ldg(&bias[col + 1]);
            const int r0 = m0 + wm * 64 + mf * 16 + er;
            const int r1 = r0 + 8;
            float2 v0 = make_float2(acc[mf][nf][0] + bx, acc[mf][nf][1] + by);
            float2 v1 = make_float2(acc[mf][nf][2] + bx, acc[mf][nf][3] + by);
            *(float2*)(C + (size_t)r0 * DIM + col) = v0;
            *(float2*)(C + (size_t)r1 * DIM + col) = v1;
        }
    }
}

// ---------------------------------------------------------------------------
// fp32 -> 3-way bf16 split
// ---------------------------------------------------------------------------
__global__ __launch_bounds__(256)
void split3_kernel(const float* __restrict__ in, __nv_bfloat16* __restrict__ h,
                   __nv_bfloat16* __restrict__ m, __nv_bfloat16* __restrict__ l,
                   size_t n)
{
    size_t i = ((size_t)blockIdx.x * 256 + threadIdx.x) * 4;
    if (i >= n) return;
    float4 v = *(const float4*)(in + i);
    float vv[4] = {v.x, v.y, v.z, v.w};
    __nv_bfloat16 hh[4], mm[4], ll[4];
#pragma unroll
    for (int j = 0; j < 4; j++) {
        float x = vv[j];
        __nv_bfloat16 a = __float2bfloat16(x);
        float r = x - __bfloat162float(a);
        __nv_bfloat16 b = __float2bfloat16(r);
        float r2 = r - __bfloat162float(b);
        __nv_bfloat16 c = __float2bfloat16(r2);
        hh[j] = a; mm[j] = b; ll[j] = c;
    }
    *(__nv_bfloat162*)(h + i)     = __nv_bfloat162(hh[0], hh[1]);
    *(__nv_bfloat162*)(h + i + 2) = __nv_bfloat162(hh[2], hh[3]);
    *(__nv_bfloat162*)(m + i)     = __nv_bfloat162(mm[0], mm[1]);
    *(__nv_bfloat162*)(m + i + 2) = __nv_bfloat162(mm[2], mm[3]);
    *(__nv_bfloat162*)(l + i)     = __nv_bfloat162(ll[0], ll[1]);
    *(__nv_bfloat162*)(l + i + 2) = __nv_bfloat162(ll[2], ll[3]);
}

// ---------------------------------------------------------------------------
// LayerNorm + ReLU + Linear(D->2)
// ---------------------------------------------------------------------------
__device__ __forceinline__ float2 block_reduce2(float a, float b)
{
    __shared__ float sa[8], sb[8];
    __syncthreads();
    int lane = threadIdx.x & 31, wd = threadIdx.x >> 5;
#pragma unroll
    for (int o = 16; o; o >>= 1) {
        a += __shfl_down_sync(0xFFFFFFFFu, a, o);
        b += __shfl_down_sync(0xFFFFFFFFu, b, o);
    }
    if (lane == 0) { sa[wd] = a; sb[wd] = b; }
    __syncthreads();
    if (wd == 0) {
        a = (lane < 8) ? sa[lane] : 0.f;
        b = (lane < 8) ? sb[lane] : 0.f;
#pragma unroll
        for (int o = 4; o; o >>= 1) {
            a += __shfl_down_sync(0xFFFFFFFFu, a, o);
            b += __shfl_down_sync(0xFFFFFFFFu, b, o);
        }
        if (lane == 0) { sa[0] = a; sb[0] = b; }
    }
    __syncthreads();
    return make_float2(sa[0], sb[0]);
}

__global__ __launch_bounds__(256)
void ln_relu_head(const float* __restrict__ H,
                  const float* __restrict__ gamma, const float* __restrict__ beta,
                  const float* __restrict__ W2, const float* __restrict__ b2,
                  float* __restrict__ logits)
{
    const int row = blockIdx.x;
    const int t   = threadIdx.x;
    const float4* h4 = (const float4*)(H + (size_t)row * DIM);

    float4 v0 = h4[t * 2];
    float4 v1 = h4[t * 2 + 1];

    float s  = v0.x + v0.y + v0.z + v0.w + v1.x + v1.y + v1.z + v1.w;
    float ss = v0.x*v0.x + v0.y*v0.y + v0.z*v0.z + v0.w*v0.w
             + v1.x*v1.x + v1.y*v1.y + v1.z*v1.z + v1.w*v1.w;

    float2 r = block_reduce2(s, ss);
    const float inv_d = 1.f / (float)DIM;
    float mu   = r.x * inv_d;
    float var  = r.y * inv_d - mu * mu;
    float rinv = rsqrtf(var + 1e-5f);

    const float4* g4  = (const float4*)gamma;
    const float4* be4 = (const float4*)beta;
    const float4* w0  = (const float4*)W2;
    const float4* w1  = (const float4*)(W2 + DIM);

    float l0 = 0.f, l1 = 0.f;
    {
        float4 g = g4[t*2], be = be4[t*2], wa = w0[t*2], wb = w1[t*2];
        float h;
        h = fmaxf(fmaf((v0.x - mu)*rinv, g.x, be.x), 0.f); l0 += h*wa.x; l1 += h*wb.x;
        h = fmaxf(fmaf((v0.y - mu)*rinv, g.y, be.y), 0.f); l0 += h*wa.y; l1 += h*wb.y;
        h = fmaxf(fmaf((v0.z - mu)*rinv, g.z, be.z), 0.f); l0 += h*wa.z; l1 += h*wb.z;
        h = fmaxf(fmaf((v0.w - mu)*rinv, g.w, be.w), 0.f); l0 += h*wa.w; l1 += h*wb.w;
    }
    {
        float4 g = g4[t*2+1], be = be4[t*2+1], wa = w0[t*2+1], wb = w1[t*2+1];
        float h;
        h = fmaxf(fmaf((v1.x - mu)*rinv, g.x, be.x), 0.f); l0 += h*wa.x; l1 += h*wb.x;
        h = fmaxf(fmaf((v1.y - mu)*rinv, g.y, be.y), 0.f); l0 += h*wa.y; l1 += h*wb.y;
        h = fmaxf(fmaf((v1.z - mu)*rinv, g.z, be.z), 0.f); l0 += h*wa.z; l1 += h*wb.z;
        h = fmaxf(fmaf((v1.w - mu)*rinv, g.w, be.w), 0.f); l0 += h*wa.w; l1 += h*wb.w;
    }

    float2 lr = block_reduce2(l0, l1);
    if (t == 0) {
        logits[row * 2 + 0] = lr.x + b2[0];
        logits[row * 2 + 1] = lr.y + b2[1];
    }
}

__global__ void combine_kernel(const float* __restrict__ lf,
                               const float* __restrict__ lfake,
                               const float* __restrict__ lreal,
                               float* __restrict__ out, int B)
{
    int b = blockIdx.x * blockDim.x + threadIdx.x;
    if (b >= B) return;
    float2 f = ((const float2*)lf)[b];
    const float2* src = (f.x >= f.y) ? (const float2*)lfake : (const float2*)lreal;
    ((float2*)out)[b] = src[b];
}

// ---------------------------------------------------------------------------
extern "C" void kernel_launch(void* const* d_in, const int* in_sizes, int n_in,
                              void* d_out, int out_size)
{
    (void)in_sizes; (void)n_in; (void)out_size;
    const float* x = (const float*)d_in[0];

    float *H = nullptr, *L = nullptr;
    __nv_bfloat16 *xs = nullptr, *ws = nullptr;
    cudaGetSymbolAddress((void**)&H,  g_H);
    cudaGetSymbolAddress((void**)&L,  g_logits);
    cudaGetSymbolAddress((void**)&xs, g_xs);
    cudaGetSymbolAddress((void**)&ws, g_ws);

    const size_t XN = (size_t)BATCH * DIM;
    const size_t WN = (size_t)DIM * DIM;
    __nv_bfloat16 *xh = xs, *xm = xs + XN, *xl = xs + 2 * XN;
    __nv_bfloat16 *wh = ws, *wm = ws + WN, *wl = ws + 2 * WN;

    constexpr int SMEM_BYTES = 4 * 16384;   // 4-stage pipeline
    cudaFuncSetAttribute(gemm_mma<3>, cudaFuncAttributeMaxDynamicSharedMemorySize, SMEM_BYTES);
    cudaFuncSetAttribute(gemm_mma<2>, cudaFuncAttributeMaxDynamicSharedMemorySize, SMEM_BYTES);

    split3_kernel<<<(int)(XN / 4 / 256), 256>>>(x, xh, xm, xl, XN);

    dim3 grid(DIM / 128, BATCH / 128);   // (16, 256)

    for (int br = 0; br < 3; br++) {
        const float* W1 = (const float*)d_in[1 + br * 6 + 0];
        const float* b1 = (const float*)d_in[1 + br * 6 + 1];
        const float* lg = (const float*)d_in[1 + br * 6 + 2];
        const float* lb = (const float*)d_in[1 + br * 6 + 3];
        const float* W2 = (const float*)d_in[1 + br * 6 + 4];
        const float* b2 = (const float*)d_in[1 + br * 6 + 5];

        split3_kernel<<<(int)(WN / 4 / 256), 256>>>(W1, wh, wm, wl, WN);

        if (br == 0)
            gemm_mma<3><<<grid, 256, SMEM_BYTES>>>(xh, xm, xl, wh, wm, wl, b1, H);
        else
            gemm_mma<2><<<grid, 256, SMEM_BYTES>>>(xh, xm, xl, wh, wm, wl, b1, H);

        ln_relu_head<<<BATCH, 256>>>(H, lg, lb, W2, b2, L + (size_t)br * BATCH * 2);
    }

    combine_kernel<<<(BATCH + 255) / 256, 256>>>(
        L, L + (size_t)BATCH * 2, L + (size_t)2 * BATCH * 2, (float*)d_out, BATCH);
}

// round 4
// speedup vs baseline: 2.5521x; 1.3823x over previous
#include <cuda_runtime.h>
#include <cuda_bf16.h>
#include <cstdint>

#define DIM   2048
#define BATCH 32768

// ---------------------------------------------------------------------------
// Device-global scratch (allocation-free rule)
// ---------------------------------------------------------------------------
__device__ __align__(16) float g_H[(size_t)BATCH * DIM];                 // 256 MB
__device__ __align__(16) float g_logits[BATCH * 2];                      // first-branch logits
__device__ __align__(16) __nv_bfloat16 g_xs[3][(size_t)BATCH * DIM];    // x splits hi/mid/lo
__device__ __align__(16) __nv_bfloat16 g_ws[3][(size_t)DIM * DIM];      // W1 splits
__device__ int g_idx[2][BATCH];                                         // fake / real row lists
__device__ int g_cnt[2];

// ---------------------------------------------------------------------------
// helpers
// ---------------------------------------------------------------------------
__device__ __forceinline__ uint32_t smem_u32_of(const void* p) {
    uint32_t a;
    asm("{ .reg .u64 t; cvta.to.shared.u64 t, %1; cvt.u32.u64 %0, t; }" : "=r"(a) : "l"(p));
    return a;
}
__device__ __forceinline__ void cp16(uint32_t dst, const void* src) {
    asm volatile("cp.async.cg.shared.global [%0], [%1], 16;" :: "r"(dst), "l"(src));
}
__device__ __forceinline__ void ldsm_x4(uint32_t* r, uint32_t addr) {
    asm volatile("ldmatrix.sync.aligned.m8n8.x4.shared.b16 {%0,%1,%2,%3}, [%4];"
                 : "=r"(r[0]), "=r"(r[1]), "=r"(r[2]), "=r"(r[3]) : "r"(addr));
}
__device__ __forceinline__ void mma16816(float* c, const uint32_t* a,
                                         uint32_t b0, uint32_t b1) {
    asm volatile("mma.sync.aligned.m16n8k16.row.col.f32.bf16.bf16.f32 "
                 "{%0,%1,%2,%3}, {%4,%5,%6,%7}, {%8,%9}, {%0,%1,%2,%3};"
                 : "+f"(c[0]), "+f"(c[1]), "+f"(c[2]), "+f"(c[3])
                 : "r"(a[0]), "r"(a[1]), "r"(a[2]), "r"(a[3]), "r"(b0), "r"(b1));
}
__device__ __forceinline__ uint32_t swz(uint32_t off) {       // Swizzle<3,4,3>
    return off ^ (((off >> 7) & 7u) << 4);
}

// ---------------------------------------------------------------------------
// Split-bf16 GEMM via mma.sync:  C[m,n] = sum_k A[m,k]*W[n,k] + bias[n]
// Virtual-K over NPROD products x 64 k-tiles (BK=32). Tile 128x128, 8 warps,
// 4-stage cp.async. GATHER: A rows taken from idx[] (compacted routing).
// ---------------------------------------------------------------------------
template<int NSPLIT, bool GATHER>
__global__ __launch_bounds__(256)
void gemm_mma(const __nv_bfloat16* __restrict__ Ah, const __nv_bfloat16* __restrict__ Am,
              const __nv_bfloat16* __restrict__ Al,
              const __nv_bfloat16* __restrict__ Bh, const __nv_bfloat16* __restrict__ Bm,
              const __nv_bfloat16* __restrict__ Bl,
              const float* __restrict__ bias, float* __restrict__ C,
              const int* __restrict__ idx, const int* __restrict__ cnt_p)
{
    constexpr int NPROD = (NSPLIT == 2) ? 3 : 6;
    constexpr int KT    = DIM / 32;
    constexpr int T     = NPROD * KT;
    constexpr int STAGE = 16384;

    extern __shared__ __align__(128) char smem[];
    __shared__ int sidx[128];
    const uint32_t sbase = smem_u32_of(smem);

    const int tid = threadIdx.x;
    const int wid = tid >> 5, lid = tid & 31;
    const int wm  = wid >> 2;
    const int wn  = wid & 3;
    const int m0  = blockIdx.y * 128;
    const int n0  = blockIdx.x * 128;

    if (GATHER) {
        const int cnt = __ldg(cnt_p);
        if (m0 >= cnt) return;
        if (tid < 128) sidx[tid] = __ldg(&idx[min(m0 + tid, cnt - 1)]);
        __syncthreads();
    }

    const int PA[6] = {0, 0, 1, 1, 0, 2};
    const int PB[6] = {0, 1, 0, 1, 2, 0};
    const __nv_bfloat16* Abase[3] = {Ah, Am, Al};
    const __nv_bfloat16* Bbase[3] = {Bh, Bm, Bl};

    const int lrow = tid >> 2;          // 0..63
    const int lch  = tid & 3;

    const int ar0 = GATHER ? sidx[lrow]      : (m0 + lrow);
    const int ar1 = GATHER ? sidx[lrow + 64] : (m0 + lrow + 64);
    const size_t aoff0 = (size_t)ar0 * DIM;
    const size_t aoff1 = (size_t)ar1 * DIM;
    const size_t boff0 = (size_t)(n0 + lrow) * DIM;
    const size_t boff1 = (size_t)(n0 + lrow + 64) * DIM;

    auto load_stage = [&](int t, int buf) {
        const int p  = t / KT;
        const int kt = t % KT;
        const size_t kofs = (size_t)kt * 32 + lch * 8;
        const __nv_bfloat16* As = Abase[PA[p]];
        const __nv_bfloat16* Bs = Bbase[PB[p]];
        const uint32_t sa = sbase + buf * STAGE;
        const uint32_t sb = sa + 8192;
        cp16(sa + swz((uint32_t)lrow * 64 + lch * 16),        As + aoff0 + kofs);
        cp16(sa + swz((uint32_t)(lrow + 64) * 64 + lch * 16), As + aoff1 + kofs);
        cp16(sb + swz((uint32_t)lrow * 64 + lch * 16),        Bs + boff0 + kofs);
        cp16(sb + swz((uint32_t)(lrow + 64) * 64 + lch * 16), Bs + boff1 + kofs);
        asm volatile("cp.async.commit_group;" ::: "memory");
    };

    float acc[4][4][4];
#pragma unroll
    for (int i = 0; i < 4; i++)
#pragma unroll
        for (int j = 0; j < 4; j++)
#pragma unroll
            for (int r = 0; r < 4; r++) acc[i][j][r] = 0.f;

    const uint32_t a_row = wm * 64 + (lid & 7) + ((lid >> 3) & 1) * 8;
    const uint32_t a_kb  = ((lid >> 4) & 1) * 16;
    const uint32_t b_row = wn * 32 + (lid & 7) + ((lid >> 4) & 1) * 8;
    const uint32_t b_kb  = ((lid >> 3) & 1) * 16;

    load_stage(0, 0);
    load_stage(1, 1);
    load_stage(2, 2);

    for (int t = 0; t < T; t++) {
        asm volatile("cp.async.wait_group 2;" ::: "memory");
        __syncthreads();

        const uint32_t sa = sbase + (t & 3) * STAGE;
        const uint32_t sb = sa + 8192;

#pragma unroll
        for (int ks = 0; ks < 2; ks++) {
            uint32_t af[4][4], bf[2][4];
#pragma unroll
            for (int mf = 0; mf < 4; mf++)
                ldsm_x4(af[mf], sa + swz((a_row + mf * 16) * 64 + ks * 32 + a_kb));
#pragma unroll
            for (int ng = 0; ng < 2; ng++)
                ldsm_x4(bf[ng], sb + swz((b_row + ng * 16) * 64 + ks * 32 + b_kb));
#pragma unroll
            for (int mf = 0; mf < 4; mf++)
#pragma unroll
                for (int nf = 0; nf < 4; nf++)
                    mma16816(acc[mf][nf], af[mf],
                             bf[nf >> 1][(nf & 1) * 2], bf[nf >> 1][(nf & 1) * 2 + 1]);
        }

        if (t + 3 < T) load_stage(t + 3, (t + 3) & 3);
    }

    const int er = lid >> 2;
    const int ec = (lid & 3) * 2;
#pragma unroll
    for (int mf = 0; mf < 4; mf++) {
#pragma unroll
        for (int nf = 0; nf < 4; nf++) {
            const int col = n0 + wn * 32 + nf * 8 + ec;
            const float bx = __ldg(&bias[col]);
            const float by = __ldg(&bias[col + 1]);
            const int r0 = m0 + wm * 64 + mf * 16 + er;   // compact row
            const int r1 = r0 + 8;
            *(float2*)(C + (size_t)r0 * DIM + col) = make_float2(acc[mf][nf][0] + bx, acc[mf][nf][1] + by);
            *(float2*)(C + (size_t)r1 * DIM + col) = make_float2(acc[mf][nf][2] + bx, acc[mf][nf][3] + by);
        }
    }
}

// ---------------------------------------------------------------------------
// fp32 -> 3-way bf16 split
// ---------------------------------------------------------------------------
__global__ __launch_bounds__(256)
void split3_kernel(const float* __restrict__ in, __nv_bfloat16* __restrict__ h,
                   __nv_bfloat16* __restrict__ m, __nv_bfloat16* __restrict__ l,
                   size_t n)
{
    size_t i = ((size_t)blockIdx.x * 256 + threadIdx.x) * 4;
    if (i >= n) return;
    float4 v = *(const float4*)(in + i);
    float vv[4] = {v.x, v.y, v.z, v.w};
    __nv_bfloat16 hh[4], mm[4], ll[4];
#pragma unroll
    for (int j = 0; j < 4; j++) {
        float x = vv[j];
        __nv_bfloat16 a = __float2bfloat16(x);
        float r = x - __bfloat162float(a);
        __nv_bfloat16 b = __float2bfloat16(r);
        float r2 = r - __bfloat162float(b);
        __nv_bfloat16 c = __float2bfloat16(r2);
        hh[j] = a; mm[j] = b; ll[j] = c;
    }
    *(__nv_bfloat162*)(h + i)     = __nv_bfloat162(hh[0], hh[1]);
    *(__nv_bfloat162*)(h + i + 2) = __nv_bfloat162(hh[2], hh[3]);
    *(__nv_bfloat162*)(m + i)     = __nv_bfloat162(mm[0], mm[1]);
    *(__nv_bfloat162*)(m + i + 2) = __nv_bfloat162(mm[2], mm[3]);
    *(__nv_bfloat162*)(l + i)     = __nv_bfloat162(ll[0], ll[1]);
    *(__nv_bfloat162*)(l + i + 2) = __nv_bfloat162(ll[2], ll[3]);
}

// ---------------------------------------------------------------------------
// LayerNorm + ReLU + Linear(D->2) core
// ---------------------------------------------------------------------------
__device__ __forceinline__ float2 block_reduce2(float a, float b)
{
    __shared__ float sa[8], sb[8];
    __syncthreads();
    int lane = threadIdx.x & 31, wd = threadIdx.x >> 5;
#pragma unroll
    for (int o = 16; o; o >>= 1) {
        a += __shfl_down_sync(0xFFFFFFFFu, a, o);
        b += __shfl_down_sync(0xFFFFFFFFu, b, o);
    }
    if (lane == 0) { sa[wd] = a; sb[wd] = b; }
    __syncthreads();
    if (wd == 0) {
        a = (lane < 8) ? sa[lane] : 0.f;
        b = (lane < 8) ? sb[lane] : 0.f;
#pragma unroll
        for (int o = 4; o; o >>= 1) {
            a += __shfl_down_sync(0xFFFFFFFFu, a, o);
            b += __shfl_down_sync(0xFFFFFFFFu, b, o);
        }
        if (lane == 0) { sa[0] = a; sb[0] = b; }
    }
    __syncthreads();
    return make_float2(sa[0], sb[0]);
}

__device__ __forceinline__ float2 ln_head_row(const float* __restrict__ H, int row,
                                              const float* __restrict__ gamma,
                                              const float* __restrict__ beta,
                                              const float* __restrict__ W2,
                                              const float* __restrict__ b2)
{
    const int t = threadIdx.x;
    const float4* h4 = (const float4*)(H + (size_t)row * DIM);
    float4 v0 = h4[t * 2];
    float4 v1 = h4[t * 2 + 1];

    float s  = v0.x + v0.y + v0.z + v0.w + v1.x + v1.y + v1.z + v1.w;
    float ss = v0.x*v0.x + v0.y*v0.y + v0.z*v0.z + v0.w*v0.w
             + v1.x*v1.x + v1.y*v1.y + v1.z*v1.z + v1.w*v1.w;

    float2 r = block_reduce2(s, ss);
    const float inv_d = 1.f / (float)DIM;
    float mu   = r.x * inv_d;
    float var  = r.y * inv_d - mu * mu;
    float rinv = rsqrtf(var + 1e-5f);

    const float4* g4  = (const float4*)gamma;
    const float4* be4 = (const float4*)beta;
    const float4* w0  = (const float4*)W2;
    const float4* w1  = (const float4*)(W2 + DIM);

    float l0 = 0.f, l1 = 0.f;
    {
        float4 g = g4[t*2], be = be4[t*2], wa = w0[t*2], wb = w1[t*2];
        float h;
        h = fmaxf(fmaf((v0.x - mu)*rinv, g.x, be.x), 0.f); l0 += h*wa.x; l1 += h*wb.x;
        h = fmaxf(fmaf((v0.y - mu)*rinv, g.y, be.y), 0.f); l0 += h*wa.y; l1 += h*wb.y;
        h = fmaxf(fmaf((v0.z - mu)*rinv, g.z, be.z), 0.f); l0 += h*wa.z; l1 += h*wb.z;
        h = fmaxf(fmaf((v0.w - mu)*rinv, g.w, be.w), 0.f); l0 += h*wa.w; l1 += h*wb.w;
    }
    {
        float4 g = g4[t*2+1], be = be4[t*2+1], wa = w0[t*2+1], wb = w1[t*2+1];
        float h;
        h = fmaxf(fmaf((v1.x - mu)*rinv, g.x, be.x), 0.f); l0 += h*wa.x; l1 += h*wb.x;
        h = fmaxf(fmaf((v1.y - mu)*rinv, g.y, be.y), 0.f); l0 += h*wa.y; l1 += h*wb.y;
        h = fmaxf(fmaf((v1.z - mu)*rinv, g.z, be.z), 0.f); l0 += h*wa.z; l1 += h*wb.z;
        h = fmaxf(fmaf((v1.w - mu)*rinv, g.w, be.w), 0.f); l0 += h*wa.w; l1 += h*wb.w;
    }

    float2 lr = block_reduce2(l0, l1);
    return make_float2(lr.x + b2[0], lr.y + b2[1]);
}

__global__ __launch_bounds__(256)
void ln_relu_head(const float* __restrict__ H,
                  const float* __restrict__ gamma, const float* __restrict__ beta,
                  const float* __restrict__ W2, const float* __restrict__ b2,
                  float* __restrict__ logits)
{
    const int row = blockIdx.x;
    float2 lr = ln_head_row(H, row, gamma, beta, W2, b2);
    if (threadIdx.x == 0) { logits[row*2] = lr.x; logits[row*2+1] = lr.y; }
}

// compact row -> scatter to out[idx[row]]
__global__ __launch_bounds__(256)
void ln_relu_head_scatter(const float* __restrict__ H,
                          const float* __restrict__ gamma, const float* __restrict__ beta,
                          const float* __restrict__ W2, const float* __restrict__ b2,
                          const int* __restrict__ idx, const int* __restrict__ cnt_p,
                          float* __restrict__ out)
{
    const int row = blockIdx.x;
    if (row >= __ldg(cnt_p)) return;
    float2 lr = ln_head_row(H, row, gamma, beta, W2, b2);
    if (threadIdx.x == 0) {
        const int o = __ldg(&idx[row]);
        out[o*2]   = lr.x;
        out[o*2+1] = lr.y;
    }
}

// ---------------------------------------------------------------------------
// Deterministic route compaction: 1 block, 1024 threads, 32 rows each.
// fake (route==0): logits[0] >= logits[1]  (argmax first-max tie rule)
// ---------------------------------------------------------------------------
__global__ __launch_bounds__(1024)
void route_scan(const float* __restrict__ L0, int* __restrict__ fake_idx,
                int* __restrict__ real_idx, int* __restrict__ cnts)
{
    __shared__ int sf[1024];
    const int t = threadIdx.x;
    uint32_t mask = 0;
    int c = 0;
#pragma unroll
    for (int j = 0; j < 32; j++) {
        const int b = t * 32 + j;
        float2 f = ((const float2*)L0)[b];
        const bool fake = (f.x >= f.y);
        mask |= (uint32_t)fake << j;
        c += fake;
    }
    sf[t] = c;
    __syncthreads();
    for (int off = 1; off < 1024; off <<= 1) {
        int v = (t >= off) ? sf[t - off] : 0;
        __syncthreads();
        sf[t] += v;
        __syncthreads();
    }
    const int total_fake = sf[1023];
    const int excl = sf[t] - c;        // #fake strictly before this thread's rows
    int fpos = excl;
#pragma unroll
    for (int j = 0; j < 32; j++) {
        const int b = t * 32 + j;
        if ((mask >> j) & 1) {
            fake_idx[fpos++] = b;
        } else {
            const int fake_before = excl + __popc(mask & ((1u << j) - 1u));
            real_idx[b - fake_before] = b;
        }
    }
    if (t == 0) { cnts[0] = total_fake; cnts[1] = BATCH - total_fake; }
}

// ---------------------------------------------------------------------------
extern "C" void kernel_launch(void* const* d_in, const int* in_sizes, int n_in,
                              void* d_out, int out_size)
{
    (void)in_sizes; (void)n_in; (void)out_size;
    const float* x = (const float*)d_in[0];

    float *H = nullptr, *L = nullptr;
    __nv_bfloat16 *xs = nullptr, *ws = nullptr;
    int *idx = nullptr, *cnt = nullptr;
    cudaGetSymbolAddress((void**)&H,   g_H);
    cudaGetSymbolAddress((void**)&L,   g_logits);
    cudaGetSymbolAddress((void**)&xs,  g_xs);
    cudaGetSymbolAddress((void**)&ws,  g_ws);
    cudaGetSymbolAddress((void**)&idx, g_idx);
    cudaGetSymbolAddress((void**)&cnt, g_cnt);

    const size_t XN = (size_t)BATCH * DIM;
    const size_t WN = (size_t)DIM * DIM;
    __nv_bfloat16 *xh = xs, *xm = xs + XN, *xl = xs + 2 * XN;
    __nv_bfloat16 *wh = ws, *wm = ws + WN, *wl = ws + 2 * WN;

    constexpr int SMEM_BYTES = 4 * 16384;
    cudaFuncSetAttribute(gemm_mma<3,false>, cudaFuncAttributeMaxDynamicSharedMemorySize, SMEM_BYTES);
    cudaFuncSetAttribute(gemm_mma<2,true>,  cudaFuncAttributeMaxDynamicSharedMemorySize, SMEM_BYTES);

    split3_kernel<<<(int)(XN / 4 / 256), 256>>>(x, xh, xm, xl, XN);

    dim3 grid(DIM / 128, BATCH / 128);

    // ---- first (routing) branch: full batch, fp32-equivalent ----
    {
        const float* W1 = (const float*)d_in[1];
        const float* b1 = (const float*)d_in[2];
        const float* lg = (const float*)d_in[3];
        const float* lb = (const float*)d_in[4];
        const float* W2 = (const float*)d_in[5];
        const float* b2 = (const float*)d_in[6];
        split3_kernel<<<(int)(WN / 4 / 256), 256>>>(W1, wh, wm, wl, WN);
        gemm_mma<3,false><<<grid, 256, SMEM_BYTES>>>(xh, xm, xl, wh, wm, wl, b1, H,
                                                     nullptr, nullptr);
        ln_relu_head<<<BATCH, 256>>>(H, lg, lb, W2, b2, L);
    }

    route_scan<<<1, 1024>>>(L, idx, idx + BATCH, cnt);

    // ---- fake (route==0) and real branches: only their rows ----
    for (int br = 1; br < 3; br++) {
        const float* W1 = (const float*)d_in[1 + br * 6 + 0];
        const float* b1 = (const float*)d_in[1 + br * 6 + 1];
        const float* lg = (const float*)d_in[1 + br * 6 + 2];
        const float* lb = (const float*)d_in[1 + br * 6 + 3];
        const float* W2 = (const float*)d_in[1 + br * 6 + 4];
        const float* b2 = (const float*)d_in[1 + br * 6 + 5];

        split3_kernel<<<(int)(WN / 4 / 256), 256>>>(W1, wh, wm, wl, WN);

        int* bidx = idx + (br - 1) * BATCH;
        int* bcnt = cnt + (br - 1);
        gemm_mma<2,true><<<grid, 256, SMEM_BYTES>>>(xh, xm, xl, wh, wm, wl, b1, H,
                                                    bidx, bcnt);
        ln_relu_head_scatter<<<BATCH, 256>>>(H, lg, lb, W2, b2, bidx, bcnt,
                                             (float*)d_out);
    }
}